// round 10
// baseline (speedup 1.0000x reference)
#include <cuda_runtime.h>
#include <math.h>

#define ADIM 6
#define ZDIM 32
#define HDIM 512
#define EDIM 1024
#define BATCH 256
#define TSTEPS 64
#define NTHR 512
#define SMEMB 53248

#define OFF_Z  (BATCH*TSTEPS*HDIM)
#define OFF_PM (OFF_Z + BATCH*TSTEPS*ZDIM)
#define OFF_PS (OFF_PM + BATCH*TSTEPS*ZDIM)
#define OFF_QM (OFF_PS + BATCH*TSTEPS*ZDIM)
#define OFF_QS (OFF_QM + BATCH*TSTEPS*ZDIM)

typedef unsigned long long ull;

// scratch. pre* layout: [t][b][h]
__device__ __align__(128) float g_preAZ[TSTEPS*BATCH*HDIM];
__device__ __align__(128) float g_preHA[TSTEPS*BATCH*HDIM];
__device__ __align__(128) float g_preHE[TSTEPS*BATCH*HDIM];
__device__ __align__(128) float g_Gp[4][BATCH*3072];
__device__ __align__(128) float g_Hp[8][BATCH*1024];
__device__ __align__(128) float g_h[BATCH*HDIM];
__device__ __align__(128) float g_x[BATCH*HDIM];
__device__ __align__(128) float g_z[BATCH*ZDIM];
__device__ __align__(128) float g_WazzT[ZDIM*HDIM];
__device__ __align__(128) float g_Wha[HDIM*HDIM];
__device__ unsigned g_arrive = 0;
__device__ volatile unsigned g_epoch = 0;

__device__ __forceinline__ float sigmoidf_(float x) { return 1.f/(1.f+expf(-x)); }
__device__ __forceinline__ float softplusf_(float x) {
    return fmaxf(x, 0.f) + log1pf(expf(-fabsf(x)));
}
__device__ __forceinline__ float4 ld4(const float* p) { return *(const float4*)p; }
__device__ __forceinline__ float2 ld2(const float* p) { return *(const float2*)p; }

__device__ __forceinline__ ull pk2(float x) {
    ull r; asm("mov.b64 %0, {%1, %1};" : "=l"(r) : "f"(x)); return r;
}
__device__ __forceinline__ void ffma2(ull &d, ull a, ull b) {
    asm("fma.rn.f32x2 %0, %1, %2, %0;" : "+l"(d) : "l"(a), "l"(b));
}
__device__ __forceinline__ void unpk2(ull v, float &lo, float &hi) {
    asm("mov.b64 {%0, %1}, %2;" : "=f"(lo), "=f"(hi) : "l"(v));
}
union F4U { float4 f; ull u[2]; };

__device__ __forceinline__ void gsync(int G) {
    __threadfence();
    __syncthreads();
    if (threadIdx.x == 0) {
        unsigned e = g_epoch;
        if (atomicAdd(&g_arrive, 1u) == (unsigned)(G - 1)) {
            g_arrive = 0;
            __threadfence();
            g_epoch = e + 1;
        } else {
            while (g_epoch == e) __nanosleep(64);
        }
        __threadfence();
    }
    __syncthreads();
}

// ---------------------------------------------------------------------------
// 128x192 tile GEMM, 512 thr, BK=16, micro 8x6 via FFMA2 (M-paired).
// A: 128 rows x K (lda), B: 192 rows x K (ldb). acc += A*B^T
// B fragment read as 3x float2 (tx*6 floats is 8B- but not 16B-aligned).
// ---------------------------------------------------------------------------
__device__ __forceinline__ void gemm128x192(
    const float* __restrict__ A, int lda, const float* __restrict__ B, int ldb,
    int KT, float* As, float* Bs, ull (&acc2)[4][6])
{
    const int tid = threadIdx.x;
    const int lrA = tid >> 2, lkA = (tid & 3) << 2;
    const int lrB = tid >> 1, lkB = (tid & 1) << 3;
    const bool bAct = (tid < 384);
    const int ty = tid >> 5, tx = tid & 31;
    const float* Ap = A + lrA*lda + lkA;
    const float* Bp = B + (bAct ? lrB : 0)*ldb + lkB;
    float4 av = ld4(Ap);
    float4 bv0 = ld4(Bp), bv1 = ld4(Bp + 4);
    #pragma unroll 1
    for (int kt = 1; kt <= KT; kt++) {
        __syncthreads();
        As[(lkA+0)*132+lrA]=av.x; As[(lkA+1)*132+lrA]=av.y;
        As[(lkA+2)*132+lrA]=av.z; As[(lkA+3)*132+lrA]=av.w;
        if (bAct) {
            Bs[(lkB+0)*196+lrB]=bv0.x; Bs[(lkB+1)*196+lrB]=bv0.y;
            Bs[(lkB+2)*196+lrB]=bv0.z; Bs[(lkB+3)*196+lrB]=bv0.w;
            Bs[(lkB+4)*196+lrB]=bv1.x; Bs[(lkB+5)*196+lrB]=bv1.y;
            Bs[(lkB+6)*196+lrB]=bv1.z; Bs[(lkB+7)*196+lrB]=bv1.w;
        }
        __syncthreads();
        if (kt < KT) {
            av = ld4(Ap + kt*16);
            bv0 = ld4(Bp + kt*16); bv1 = ld4(Bp + kt*16 + 4);
        }
        #pragma unroll
        for (int kk = 0; kk < 16; kk++) {
            F4U a0, a1;
            a0.f = ld4(As + kk*132 + ty*8);
            a1.f = ld4(As + kk*132 + ty*8 + 4);
            const float* brow = Bs + kk*196 + tx*6;
            float2 bA = ld2(brow), bB = ld2(brow + 2), bC = ld2(brow + 4);
            ull au0 = a0.u[0], au1 = a0.u[1], au2 = a1.u[0], au3 = a1.u[1];
            ull b0 = pk2(bA.x), b1 = pk2(bA.y), b2u = pk2(bB.x);
            ull b3 = pk2(bB.y), b4u = pk2(bC.x), b5 = pk2(bC.y);
            ffma2(acc2[0][0], au0, b0); ffma2(acc2[0][1], au0, b1); ffma2(acc2[0][2], au0, b2u);
            ffma2(acc2[0][3], au0, b3); ffma2(acc2[0][4], au0, b4u); ffma2(acc2[0][5], au0, b5);
            ffma2(acc2[1][0], au1, b0); ffma2(acc2[1][1], au1, b1); ffma2(acc2[1][2], au1, b2u);
            ffma2(acc2[1][3], au1, b3); ffma2(acc2[1][4], au1, b4u); ffma2(acc2[1][5], au1, b5);
            ffma2(acc2[2][0], au2, b0); ffma2(acc2[2][1], au2, b1); ffma2(acc2[2][2], au2, b2u);
            ffma2(acc2[2][3], au2, b3); ffma2(acc2[2][4], au2, b4u); ffma2(acc2[2][5], au2, b5);
            ffma2(acc2[3][0], au3, b0); ffma2(acc2[3][1], au3, b1); ffma2(acc2[3][2], au3, b2u);
            ffma2(acc2[3][3], au3, b3); ffma2(acc2[3][4], au3, b4u); ffma2(acc2[3][5], au3, b5);
        }
    }
}

// 128x128 tile GEMM, 512 thr, BK=16, micro 8x4 via FFMA2 (M-paired). acc += A*B^T
__device__ __forceinline__ void gemm128(
    const float* __restrict__ A, int lda, const float* __restrict__ B, int ldb,
    int KT, float* As, float* Bs, ull (&acc2)[4][4])
{
    const int tid = threadIdx.x;
    const int lr = tid >> 2, lk = (tid & 3) << 2;
    const int ty = tid >> 5, tx = tid & 31;
    const float* Ap = A + lr*lda + lk;
    const float* Bp = B + lr*ldb + lk;
    float4 av = ld4(Ap), bv = ld4(Bp);
    #pragma unroll 1
    for (int kt = 1; kt <= KT; kt++) {
        __syncthreads();
        As[(lk+0)*132+lr]=av.x; As[(lk+1)*132+lr]=av.y; As[(lk+2)*132+lr]=av.z; As[(lk+3)*132+lr]=av.w;
        Bs[(lk+0)*132+lr]=bv.x; Bs[(lk+1)*132+lr]=bv.y; Bs[(lk+2)*132+lr]=bv.z; Bs[(lk+3)*132+lr]=bv.w;
        __syncthreads();
        if (kt < KT) { av = ld4(Ap + kt*16); bv = ld4(Bp + kt*16); }
        #pragma unroll
        for (int kk = 0; kk < 16; kk++) {
            F4U a0, a1, b;
            a0.f = ld4(As + kk*132 + ty*8);
            a1.f = ld4(As + kk*132 + ty*8 + 4);
            b.f  = ld4(Bs + kk*132 + tx*4);
            ull au0 = a0.u[0], au1 = a0.u[1], au2 = a1.u[0], au3 = a1.u[1];
            ull b0 = pk2(b.f.x), b1 = pk2(b.f.y), b2 = pk2(b.f.z), b3 = pk2(b.f.w);
            ffma2(acc2[0][0], au0, b0); ffma2(acc2[0][1], au0, b1);
            ffma2(acc2[0][2], au0, b2); ffma2(acc2[0][3], au0, b3);
            ffma2(acc2[1][0], au1, b0); ffma2(acc2[1][1], au1, b1);
            ffma2(acc2[1][2], au1, b2); ffma2(acc2[1][3], au1, b3);
            ffma2(acc2[2][0], au2, b0); ffma2(acc2[2][1], au2, b1);
            ffma2(acc2[2][2], au2, b2); ffma2(acc2[2][3], au2, b3);
            ffma2(acc2[3][0], au3, b0); ffma2(acc2[3][1], au3, b1);
            ffma2(acc2[3][2], au3, b2); ffma2(acc2[3][3], au3, b3);
        }
    }
}

__device__ __forceinline__ void unpack_acc(ull (&acc2)[4][4], float (&r)[8][4]) {
    #pragma unroll
    for (int ip = 0; ip < 4; ip++)
        #pragma unroll
        for (int j = 0; j < 4; j++)
            unpk2(acc2[ip][j], r[2*ip][j], r[2*ip+1][j]);
}
__device__ __forceinline__ void unpack_acc6(ull (&acc2)[4][6], float (&r)[8][6]) {
    #pragma unroll
    for (int ip = 0; ip < 4; ip++)
        #pragma unroll
        for (int j = 0; j < 6; j++)
            unpk2(acc2[ip][j], r[2*ip][j], r[2*ip+1][j]);
}

__device__ __forceinline__ float gru1(float ir, float iz, float inn,
                                      float hr, float hz, float hn, float hp) {
    float rr = sigmoidf_(ir + hr);
    float u = sigmoidf_(iz + hz);
    float n = tanhf(inn + rr*hn);
    return (1.f - u)*n + u*hp;
}

__global__ __launch_bounds__(NTHR, 1) void rssm_kernel(
    const float* __restrict__ prev_z, const float* __restrict__ prev_h,
    const float* __restrict__ actions, const float* __restrict__ emb,
    const float* __restrict__ dones, const float* __restrict__ post_noise,
    const float* __restrict__ W_az, const float* __restrict__ b_az,
    const float* __restrict__ W_ih, const float* __restrict__ W_hh,
    const float* __restrict__ b_ih, const float* __restrict__ b_hh,
    const float* __restrict__ W_ha, const float* __restrict__ b_ha,
    const float* __restrict__ W_prior, const float* __restrict__ b_prior,
    const float* __restrict__ W_he, const float* __restrict__ b_he,
    const float* __restrict__ W_post, const float* __restrict__ b_post,
    float* __restrict__ out)
{
    extern __shared__ __align__(16) float sm[];
    const int tid = threadIdx.x, bid = blockIdx.x, G = gridDim.x;
    const int gthr = G*NTHR, gtid = bid*NTHR + tid;
    float* As = sm;            // 16*132
    float* Bs = sm + 2112;     // 16*196 max

    // ===== P0: init, pack, action projections, preHE =====
    for (int i = gtid; i < BATCH*HDIM; i += gthr) g_h[i] = prev_h[i];
    for (int i = gtid; i < BATCH*ZDIM; i += gthr) g_z[i] = prev_z[i];
    for (int i = gtid; i < HDIM*HDIM; i += gthr)
        g_Wha[i] = W_ha[(i >> 9)*(HDIM+ADIM) + (i & 511)];
    for (int i = gtid; i < ZDIM*HDIM; i += gthr)
        g_WazzT[i] = W_az[(i & 511)*(ZDIM+ADIM) + (i >> 9)];
    for (int tt = bid; tt < TSTEPS; tt += G) {
        float* waz = sm, *wha = sm + 3072, *actS = sm + 6144;
        __syncthreads();
        for (int e = tid; e < HDIM*ADIM; e += NTHR) {
            int h = e / ADIM, j = e - h*ADIM;
            waz[e] = W_az[h*(ZDIM+ADIM) + ZDIM + j];
            wha[e] = W_ha[h*(HDIM+ADIM) + HDIM + j];
        }
        for (int e = tid; e < BATCH*ADIM; e += NTHR) {
            int b = e / ADIM, j = e - b*ADIM;
            actS[e] = actions[(b*TSTEPS + tt)*ADIM + j];
        }
        __syncthreads();
        for (int e = tid; e < BATCH*HDIM; e += NTHR) {
            int b = e >> 9, h = e & 511;
            float pa = b_az[h], ph = b_ha[h];
            #pragma unroll
            for (int j = 0; j < ADIM; j++) {
                float a = actS[b*ADIM + j];
                pa += a * waz[h*ADIM + j];
                ph += a * wha[h*ADIM + j];
            }
            int o = (tt*BATCH + b)*HDIM + h;
            g_preAZ[o] = pa; g_preHA[o] = ph;
        }
        __syncthreads();
    }
    // preHE: 512 tasks = 128 m-tiles x 4 n-tiles, K=1024 (KT=64)
    for (int task = bid; task < 512; task += G) {
        int n = task & 3, m = task >> 2;
        ull acc2[4][4] = {};
        gemm128(emb + (size_t)m*128*EDIM, EDIM,
                W_he + (size_t)n*128*1536 + 512, 1536, 64, As, Bs, acc2);
        float r[8][4]; unpack_acc(acc2, r);
        int ty = tid >> 5, tx = tid & 31;
        float4 bh = ld4(b_he + n*128 + tx*4);
        #pragma unroll
        for (int i = 0; i < 8; i++) {
            int rr = m*128 + ty*8 + i;
            int o = ((rr & 63)*BATCH + (rr >> 6))*HDIM + n*128 + tx*4;
            *(float4*)(g_preHE + o) = make_float4(r[i][0]+bh.x, r[i][1]+bh.y,
                                                  r[i][2]+bh.z, r[i][3]+bh.w);
        }
    }
    gsync(G);
    // ===== P1: x(0) =====
    for (int i = gtid; i < BATCH*HDIM; i += gthr) {
        int b = i >> 9, c = i & 511;
        float d = 1.f - dones[b*TSTEPS];
        float acx = g_preAZ[b*HDIM + c];
        #pragma unroll 8
        for (int k = 0; k < ZDIM; k++)
            acx += (g_z[b*ZDIM + k]*d) * g_WazzT[k*HDIM + c];
        g_x[i] = fmaxf(acx, 0.f);
    }
    gsync(G);

    for (int t = 0; t < TSTEPS; t++) {
        // ---- A: gate partials. 128 tasks = 32 tiles(128x192) x Ksplit4 (K=128) ----
        for (int task = bid; task < 128; task += G) {
            int kc = task & 3, tile = task >> 2;
            int n = tile & 15, m = tile >> 4;
            const float* Aptr = ((n < 8) ? g_x : g_h) + (size_t)m*128*HDIM + kc*128;
            const float* Bptr = ((n < 8) ? W_ih + (size_t)n*192*HDIM
                                         : W_hh + (size_t)(n-8)*192*HDIM) + kc*128;
            ull acc2[4][6] = {};
            gemm128x192(Aptr, HDIM, Bptr, HDIM, 8, As, Bs, acc2);
            float r[8][6]; unpack_acc6(acc2, r);
            int ty = tid >> 5, tx = tid & 31;
            int cb = n*192 + tx*6;
            #pragma unroll
            for (int i = 0; i < 8; i++) {
                float* dst = &g_Gp[kc][(m*128 + ty*8 + i)*3072 + cb];
                *(float2*)(dst)     = make_float2(r[i][0], r[i][1]);
                *(float2*)(dst + 2) = make_float2(r[i][2], r[i][3]);
                *(float2*)(dst + 4) = make_float2(r[i][4], r[i][5]);
            }
        }
        gsync(G);
        // ---- B: combine 4 partials + GRU fuse + h_seq ----
        for (int i = gtid; i < BATCH*HDIM/4; i += gthr) {
            int b = i >> 7, j4 = (i & 127) << 2;
            const float* p0 = g_Gp[0] + b*3072 + j4;
            const float* p1 = g_Gp[1] + b*3072 + j4;
            const float* p2 = g_Gp[2] + b*3072 + j4;
            const float* p3 = g_Gp[3] + b*3072 + j4;
            float4 gg[6];
            #pragma unroll
            for (int q = 0; q < 6; q++) {
                float4 a = ld4(p0 + q*512), bb = ld4(p1 + q*512);
                float4 c = ld4(p2 + q*512), dd = ld4(p3 + q*512);
                gg[q] = make_float4(a.x+bb.x+c.x+dd.x, a.y+bb.y+c.y+dd.y,
                                    a.z+bb.z+c.z+dd.z, a.w+bb.w+c.w+dd.w);
            }
            float4 bir = ld4(b_ih + j4), biz = ld4(b_ih + 512 + j4), bin = ld4(b_ih + 1024 + j4);
            float4 bhr = ld4(b_hh + j4), bhz = ld4(b_hh + 512 + j4), bhn = ld4(b_hh + 1024 + j4);
            float4 hp = ld4(g_h + i*4);
            float4 hv;
            hv.x = gru1(gg[0].x+bir.x, gg[1].x+biz.x, gg[2].x+bin.x, gg[3].x+bhr.x, gg[4].x+bhz.x, gg[5].x+bhn.x, hp.x);
            hv.y = gru1(gg[0].y+bir.y, gg[1].y+biz.y, gg[2].y+bin.y, gg[3].y+bhr.y, gg[4].y+bhz.y, gg[5].y+bhn.y, hp.y);
            hv.z = gru1(gg[0].z+bir.z, gg[1].z+biz.z, gg[2].z+bin.z, gg[3].z+bhr.z, gg[4].z+bhz.z, gg[5].z+bhn.z, hp.z);
            hv.w = gru1(gg[0].w+bir.w, gg[1].w+biz.w, gg[2].w+bin.w, gg[3].w+bhr.w, gg[4].w+bhz.w, gg[5].w+bhn.w, hp.w);
            *(float4*)(g_h + i*4) = hv;
            *(float4*)(out + (b*TSTEPS + t)*HDIM + j4) = hv;
        }
        gsync(G);
        // ---- C: hahe partials. 128 tasks = 16 tiles(128x128) x Ksplit8 (K=64) ----
        for (int task = bid; task < 128; task += G) {
            int kc = task & 7, tile = task >> 3;
            int n = tile & 7, m = tile >> 3;
            const float* Bptr = (n < 4) ? g_Wha + (size_t)n*128*HDIM + kc*64
                                        : W_he + (size_t)(n-4)*128*1536 + kc*64;
            ull acc2[4][4] = {};
            gemm128(g_h + (size_t)m*128*HDIM + kc*64, HDIM,
                    Bptr, (n < 4) ? HDIM : 1536, 4, As, Bs, acc2);
            float r[8][4]; unpack_acc(acc2, r);
            int ty = tid >> 5, tx = tid & 31;
            #pragma unroll
            for (int i = 0; i < 8; i++)
                *(float4*)&g_Hp[kc][(m*128 + ty*8 + i)*1024 + n*128 + tx*4] =
                    make_float4(r[i][0], r[i][1], r[i][2], r[i][3]);
        }
        gsync(G);
        // ---- D: 64 tasks x 4 rows: combine+relu, heads, z, x[t+1] ----
        for (int task = bid; task < 64; task += G) {
            int r0 = task*4;
            float* A8 = sm;          // 4 x 1028
            float* Ws = sm + 4112;   // 128 x 68
            __syncthreads();
            for (int e = tid; e < 4*1024; e += NTHR) {
                int r = e >> 10, c = e & 1023;
                int ro = (r0 + r)*1024 + c;
                float v = g_Hp[0][ro] + g_Hp[1][ro] + g_Hp[2][ro] + g_Hp[3][ro]
                        + g_Hp[4][ro] + g_Hp[5][ro] + g_Hp[6][ro] + g_Hp[7][ro];
                v += (c < 512) ? g_preHA[(t*BATCH + r0+r)*HDIM + c]
                               : g_preHE[(t*BATCH + r0+r)*HDIM + c - 512];
                A8[r*1028 + c] = fmaxf(v, 0.f);
            }
            const int c = tid & 127, rg = tid >> 7;
            const int aoff = (c < 64) ? 0 : 512;
            float acc = 0.f;
            for (int ch = 0; ch < 8; ch++) {
                __syncthreads();
                for (int e = tid; e < 512; e += NTHR) {
                    int c2 = e >> 2, k4 = (e & 3) << 4;
                    const float* Wr = (c2 < 64) ? W_prior + c2*HDIM : W_post + (c2-64)*HDIM;
                    #pragma unroll
                    for (int q = 0; q < 4; q++) {
                        float4 w = ld4(Wr + ch*64 + k4 + q*4);
                        Ws[c2*68 + k4 + q*4]   = w.x; Ws[c2*68 + k4 + q*4+1] = w.y;
                        Ws[c2*68 + k4 + q*4+2] = w.z; Ws[c2*68 + k4 + q*4+3] = w.w;
                    }
                }
                __syncthreads();
                const float* ab = A8 + rg*1028 + aoff + ch*64;
                #pragma unroll
                for (int k4 = 0; k4 < 64; k4 += 4) {
                    float4 w = ld4(Ws + c*68 + k4);
                    float4 a = ld4(ab + k4);
                    acc += a.x*w.x + a.y*w.y + a.z*w.z + a.w*w.w;
                }
            }
            __syncthreads();
            float* Q  = sm;        // 4 x 64 (A8 dead)
            float* zm = sm + 256;  // 4 x 32
            {
                int b = r0 + rg;
                float v = acc + ((c < 64) ? b_prior[c] : b_post[c-64]);
                if (c < 32)       out[OFF_PM + (b*TSTEPS + t)*ZDIM + c] = v;
                else if (c < 64)  out[OFF_PS + (b*TSTEPS + t)*ZDIM + c-32] = softplusf_(v);
                else              Q[rg*64 + (c-64)] = v;
            }
            __syncthreads();
            if (tid < 128) {
                int r = tid >> 5, j = tid & 31, b = r0 + r;
                float qm = Q[r*64 + j];
                float qs = softplusf_(Q[r*64 + 32 + j]);
                float z = qm + qs * post_noise[(b*TSTEPS + t)*ZDIM + j];
                int o = (b*TSTEPS + t)*ZDIM + j;
                out[OFF_QM + o] = qm; out[OFF_QS + o] = qs; out[OFF_Z + o] = z;
                if (t + 1 < TSTEPS)
                    zm[r*32 + j] = z * (1.f - dones[b*TSTEPS + t + 1]);
            }
            __syncthreads();
            if (t + 1 < TSTEPS) {
                for (int e = tid; e < 4*HDIM; e += NTHR) {
                    int r = e >> 9, cc = e & 511;
                    float acx = g_preAZ[((t+1)*BATCH + r0+r)*HDIM + cc];
                    #pragma unroll 8
                    for (int k = 0; k < ZDIM; k++)
                        acx += zm[r*32 + k] * g_WazzT[k*HDIM + cc];
                    g_x[(r0+r)*HDIM + cc] = fmaxf(acx, 0.f);
                }
            }
            __syncthreads();
        }
        gsync(G);
    }
}

extern "C" void kernel_launch(void* const* d_in, const int* in_sizes, int n_in,
                              void* d_out, int out_size) {
    const float* prev_z = (const float*)d_in[0];
    const float* prev_h = (const float*)d_in[1];
    const float* actions = (const float*)d_in[2];
    const float* emb = (const float*)d_in[3];
    const float* dones = (const float*)d_in[4];
    const float* post_noise = (const float*)d_in[6];
    const float* W_az = (const float*)d_in[7];
    const float* b_az = (const float*)d_in[8];
    const float* W_ih = (const float*)d_in[9];
    const float* W_hh = (const float*)d_in[10];
    const float* b_ih = (const float*)d_in[11];
    const float* b_hh = (const float*)d_in[12];
    const float* W_ha = (const float*)d_in[13];
    const float* b_ha = (const float*)d_in[14];
    const float* W_prior = (const float*)d_in[15];
    const float* b_prior = (const float*)d_in[16];
    const float* W_he = (const float*)d_in[17];
    const float* b_he = (const float*)d_in[18];
    const float* W_post = (const float*)d_in[19];
    const float* b_post = (const float*)d_in[20];
    float* out = (float*)d_out;

    cudaFuncSetAttribute(rssm_kernel, cudaFuncAttributeMaxDynamicSharedMemorySize, SMEMB);
    int dev = 0, nsm = 0, occ = 0;
    cudaGetDevice(&dev);
    cudaDeviceGetAttribute(&nsm, cudaDevAttrMultiProcessorCount, dev);
    cudaOccupancyMaxActiveBlocksPerMultiprocessor(&occ, rssm_kernel, NTHR, SMEMB);
    if (occ < 1) occ = 1;
    int G = nsm * occ;
    if (G > 148) G = 148;
    rssm_kernel<<<G, NTHR, SMEMB>>>(prev_z, prev_h, actions, emb, dones, post_noise,
                                    W_az, b_az, W_ih, W_hh, b_ih, b_hh, W_ha, b_ha,
                                    W_prior, b_prior, W_he, b_he, W_post, b_post, out);
}

// round 11
// speedup vs baseline: 1.0533x; 1.0533x over previous
#include <cuda_runtime.h>
#include <math.h>

#define ADIM 6
#define ZDIM 32
#define HDIM 512
#define EDIM 1024
#define BATCH 256
#define TSTEPS 64
#define NTHR 512
#define SMEMB 53248

#define OFF_Z  (BATCH*TSTEPS*HDIM)
#define OFF_PM (OFF_Z + BATCH*TSTEPS*ZDIM)
#define OFF_PS (OFF_PM + BATCH*TSTEPS*ZDIM)
#define OFF_QM (OFF_PS + BATCH*TSTEPS*ZDIM)
#define OFF_QS (OFF_QM + BATCH*TSTEPS*ZDIM)

typedef unsigned long long ull;

// scratch. pre* layout: [t][b][h]
__device__ __align__(128) float g_preAZ[TSTEPS*BATCH*HDIM];
__device__ __align__(128) float g_preHA[TSTEPS*BATCH*HDIM];
__device__ __align__(128) float g_preHE[TSTEPS*BATCH*HDIM];
__device__ __align__(128) float g_Gp[3][BATCH*3072];
__device__ __align__(128) float g_Hp[8][BATCH*1024];
__device__ __align__(128) float g_h[BATCH*HDIM];
__device__ __align__(128) float g_x[BATCH*HDIM];
__device__ __align__(128) float g_z[BATCH*ZDIM];
__device__ __align__(128) float g_WazzT[ZDIM*HDIM];
__device__ __align__(128) float g_Wha[HDIM*HDIM];
// distributed barrier state: per-block epoch flags + global epoch (monotonic)
__device__ volatile unsigned g_flags[256];
__device__ volatile unsigned g_epoch;

__device__ __forceinline__ float sigmoidf_(float x) { return 1.f/(1.f+expf(-x)); }
__device__ __forceinline__ float softplusf_(float x) {
    return fmaxf(x, 0.f) + log1pf(expf(-fabsf(x)));
}
__device__ __forceinline__ float4 ld4(const float* p) { return *(const float4*)p; }

__device__ __forceinline__ ull pk2(float x) {
    ull r; asm("mov.b64 %0, {%1, %1};" : "=l"(r) : "f"(x)); return r;
}
__device__ __forceinline__ void ffma2(ull &d, ull a, ull b) {
    asm("fma.rn.f32x2 %0, %1, %2, %0;" : "+l"(d) : "l"(a), "l"(b));
}
__device__ __forceinline__ void unpk2(ull v, float &lo, float &hi) {
    asm("mov.b64 {%0, %1}, %2;" : "=f"(lo), "=f"(hi) : "l"(v));
}
union F4U { float4 f; ull u[2]; };

// Distributed flag barrier. Each block publishes its arrival to its own slot
// (no atomic contention); block 0's threads poll all slots in parallel, then
// block 0 bumps the epoch. Monotonic counters -> no reset race: a block can
// only arrive at barrier N+1 after epoch reached N, which requires all flags
// to have reached N first.
__device__ __forceinline__ void gsync(int G) {
    __syncthreads();
    __threadfence();
    unsigned e = g_epoch;
    if (blockIdx.x == 0) {
        int s = threadIdx.x;
        if (s >= 1 && s < G) {
            while (g_flags[s] <= e) __nanosleep(32);
        }
        __syncthreads();
        if (threadIdx.x == 0) {
            __threadfence();
            g_epoch = e + 1;
        }
        __syncthreads();
    } else {
        if (threadIdx.x == 0) {
            g_flags[blockIdx.x] = e + 1;
            while (g_epoch <= e) __nanosleep(32);
        }
        __syncthreads();
    }
    __threadfence();
}

// 128x128 tile GEMM, 512 thr, BK=16, micro 8x4 via FFMA2 (M-paired). acc += A*B^T
__device__ __forceinline__ void gemm128(
    const float* __restrict__ A, int lda, const float* __restrict__ B, int ldb,
    int KT, float* As, float* Bs, ull (&acc2)[4][4])
{
    const int tid = threadIdx.x;
    const int lr = tid >> 2, lk = (tid & 3) << 2;
    const int ty = tid >> 5, tx = tid & 31;
    const float* Ap = A + lr*lda + lk;
    const float* Bp = B + lr*ldb + lk;
    float4 av = ld4(Ap), bv = ld4(Bp);
    #pragma unroll 1
    for (int kt = 1; kt <= KT; kt++) {
        __syncthreads();
        As[(lk+0)*132+lr]=av.x; As[(lk+1)*132+lr]=av.y; As[(lk+2)*132+lr]=av.z; As[(lk+3)*132+lr]=av.w;
        Bs[(lk+0)*132+lr]=bv.x; Bs[(lk+1)*132+lr]=bv.y; Bs[(lk+2)*132+lr]=bv.z; Bs[(lk+3)*132+lr]=bv.w;
        __syncthreads();
        if (kt < KT) { av = ld4(Ap + kt*16); bv = ld4(Bp + kt*16); }
        #pragma unroll
        for (int kk = 0; kk < 16; kk++) {
            F4U a0, a1, b;
            a0.f = ld4(As + kk*132 + ty*8);
            a1.f = ld4(As + kk*132 + ty*8 + 4);
            b.f  = ld4(Bs + kk*132 + tx*4);
            ull au0 = a0.u[0], au1 = a0.u[1], au2 = a1.u[0], au3 = a1.u[1];
            ull b0 = pk2(b.f.x), b1 = pk2(b.f.y), b2 = pk2(b.f.z), b3 = pk2(b.f.w);
            ffma2(acc2[0][0], au0, b0); ffma2(acc2[0][1], au0, b1);
            ffma2(acc2[0][2], au0, b2); ffma2(acc2[0][3], au0, b3);
            ffma2(acc2[1][0], au1, b0); ffma2(acc2[1][1], au1, b1);
            ffma2(acc2[1][2], au1, b2); ffma2(acc2[1][3], au1, b3);
            ffma2(acc2[2][0], au2, b0); ffma2(acc2[2][1], au2, b1);
            ffma2(acc2[2][2], au2, b2); ffma2(acc2[2][3], au2, b3);
            ffma2(acc2[3][0], au3, b0); ffma2(acc2[3][1], au3, b1);
            ffma2(acc2[3][2], au3, b2); ffma2(acc2[3][3], au3, b3);
        }
    }
}

__device__ __forceinline__ void unpack_acc(ull (&acc2)[4][4], float (&r)[8][4]) {
    #pragma unroll
    for (int ip = 0; ip < 4; ip++)
        #pragma unroll
        for (int j = 0; j < 4; j++)
            unpk2(acc2[ip][j], r[2*ip][j], r[2*ip+1][j]);
}

__device__ __forceinline__ float gru1(float ir, float iz, float inn,
                                      float hr, float hz, float hn, float hp) {
    float rr = sigmoidf_(ir + hr);
    float u = sigmoidf_(iz + hz);
    float n = tanhf(inn + rr*hn);
    return (1.f - u)*n + u*hp;
}

__constant__ int c_kofs[3] = {0, 176, 352};
__constant__ int c_kcnt[3] = {11, 11, 10};

__global__ __launch_bounds__(NTHR, 1) void rssm_kernel(
    const float* __restrict__ prev_z, const float* __restrict__ prev_h,
    const float* __restrict__ actions, const float* __restrict__ emb,
    const float* __restrict__ dones, const float* __restrict__ post_noise,
    const float* __restrict__ W_az, const float* __restrict__ b_az,
    const float* __restrict__ W_ih, const float* __restrict__ W_hh,
    const float* __restrict__ b_ih, const float* __restrict__ b_hh,
    const float* __restrict__ W_ha, const float* __restrict__ b_ha,
    const float* __restrict__ W_prior, const float* __restrict__ b_prior,
    const float* __restrict__ W_he, const float* __restrict__ b_he,
    const float* __restrict__ W_post, const float* __restrict__ b_post,
    float* __restrict__ out)
{
    extern __shared__ __align__(16) float sm[];
    const int tid = threadIdx.x, bid = blockIdx.x, G = gridDim.x;
    const int gthr = G*NTHR, gtid = bid*NTHR + tid;
    float* As = sm;            // 16*132
    float* Bs = sm + 2112;     // 16*132

    // ===== P0: init, pack, action projections, preHE =====
    for (int i = gtid; i < BATCH*HDIM; i += gthr) g_h[i] = prev_h[i];
    for (int i = gtid; i < BATCH*ZDIM; i += gthr) g_z[i] = prev_z[i];
    for (int i = gtid; i < HDIM*HDIM; i += gthr)
        g_Wha[i] = W_ha[(i >> 9)*(HDIM+ADIM) + (i & 511)];
    for (int i = gtid; i < ZDIM*HDIM; i += gthr)
        g_WazzT[i] = W_az[(i & 511)*(ZDIM+ADIM) + (i >> 9)];
    for (int tt = bid; tt < TSTEPS; tt += G) {
        float* waz = sm, *wha = sm + 3072, *actS = sm + 6144;
        __syncthreads();
        for (int e = tid; e < HDIM*ADIM; e += NTHR) {
            int h = e / ADIM, j = e - h*ADIM;
            waz[e] = W_az[h*(ZDIM+ADIM) + ZDIM + j];
            wha[e] = W_ha[h*(HDIM+ADIM) + HDIM + j];
        }
        for (int e = tid; e < BATCH*ADIM; e += NTHR) {
            int b = e / ADIM, j = e - b*ADIM;
            actS[e] = actions[(b*TSTEPS + tt)*ADIM + j];
        }
        __syncthreads();
        for (int e = tid; e < BATCH*HDIM; e += NTHR) {
            int b = e >> 9, h = e & 511;
            float pa = b_az[h], ph = b_ha[h];
            #pragma unroll
            for (int j = 0; j < ADIM; j++) {
                float a = actS[b*ADIM + j];
                pa += a * waz[h*ADIM + j];
                ph += a * wha[h*ADIM + j];
            }
            int o = (tt*BATCH + b)*HDIM + h;
            g_preAZ[o] = pa; g_preHA[o] = ph;
        }
        __syncthreads();
    }
    // preHE: 512 tasks = 128 m-tiles x 4 n-tiles, K=1024 (KT=64)
    for (int task = bid; task < 512; task += G) {
        int n = task & 3, m = task >> 2;
        ull acc2[4][4] = {};
        gemm128(emb + (size_t)m*128*EDIM, EDIM,
                W_he + (size_t)n*128*1536 + 512, 1536, 64, As, Bs, acc2);
        float r[8][4]; unpack_acc(acc2, r);
        int ty = tid >> 5, tx = tid & 31;
        float4 bh = ld4(b_he + n*128 + tx*4);
        #pragma unroll
        for (int i = 0; i < 8; i++) {
            int rr = m*128 + ty*8 + i;
            int o = ((rr & 63)*BATCH + (rr >> 6))*HDIM + n*128 + tx*4;
            *(float4*)(g_preHE + o) = make_float4(r[i][0]+bh.x, r[i][1]+bh.y,
                                                  r[i][2]+bh.z, r[i][3]+bh.w);
        }
    }
    gsync(G);
    // ===== P1: x(0) =====
    for (int i = gtid; i < BATCH*HDIM; i += gthr) {
        int b = i >> 9, c = i & 511;
        float d = 1.f - dones[b*TSTEPS];
        float acx = g_preAZ[b*HDIM + c];
        #pragma unroll 8
        for (int k = 0; k < ZDIM; k++)
            acx += (g_z[b*ZDIM + k]*d) * g_WazzT[k*HDIM + c];
        g_x[i] = fmaxf(acx, 0.f);
    }
    gsync(G);

    for (int t = 0; t < TSTEPS; t++) {
        // ---- A: gate partials. 144 tasks = 48 tiles(128x128) x Ksplit3 ----
        for (int task = bid; task < 144; task += G) {
            int kc = task % 3, tile = task / 3;
            int n = tile % 24, m = tile / 24;
            int ko = c_kofs[kc];
            const float* Aptr = ((n < 12) ? g_x : g_h) + (size_t)m*128*HDIM + ko;
            const float* Bptr = ((n < 12) ? W_ih + (size_t)n*128*HDIM
                                          : W_hh + (size_t)(n-12)*128*HDIM) + ko;
            ull acc2[4][4] = {};
            gemm128(Aptr, HDIM, Bptr, HDIM, c_kcnt[kc], As, Bs, acc2);
            float r[8][4]; unpack_acc(acc2, r);
            int ty = tid >> 5, tx = tid & 31;
            #pragma unroll
            for (int i = 0; i < 8; i++)
                *(float4*)&g_Gp[kc][(m*128 + ty*8 + i)*3072 + n*128 + tx*4] =
                    make_float4(r[i][0], r[i][1], r[i][2], r[i][3]);
        }
        gsync(G);
        // ---- B: combine 3 partials + GRU fuse + h_seq ----
        for (int i = gtid; i < BATCH*HDIM/4; i += gthr) {
            int b = i >> 7, j4 = (i & 127) << 2;
            const float* p0 = g_Gp[0] + b*3072 + j4;
            const float* p1 = g_Gp[1] + b*3072 + j4;
            const float* p2 = g_Gp[2] + b*3072 + j4;
            float4 gg[6];
            #pragma unroll
            for (int q = 0; q < 6; q++) {
                float4 a = ld4(p0 + q*512), bb = ld4(p1 + q*512), c = ld4(p2 + q*512);
                gg[q] = make_float4(a.x+bb.x+c.x, a.y+bb.y+c.y, a.z+bb.z+c.z, a.w+bb.w+c.w);
            }
            float4 bir = ld4(b_ih + j4), biz = ld4(b_ih + 512 + j4), bin = ld4(b_ih + 1024 + j4);
            float4 bhr = ld4(b_hh + j4), bhz = ld4(b_hh + 512 + j4), bhn = ld4(b_hh + 1024 + j4);
            float4 hp = ld4(g_h + i*4);
            float4 hv;
            hv.x = gru1(gg[0].x+bir.x, gg[1].x+biz.x, gg[2].x+bin.x, gg[3].x+bhr.x, gg[4].x+bhz.x, gg[5].x+bhn.x, hp.x);
            hv.y = gru1(gg[0].y+bir.y, gg[1].y+biz.y, gg[2].y+bin.y, gg[3].y+bhr.y, gg[4].y+bhz.y, gg[5].y+bhn.y, hp.y);
            hv.z = gru1(gg[0].z+bir.z, gg[1].z+biz.z, gg[2].z+bin.z, gg[3].z+bhr.z, gg[4].z+bhz.z, gg[5].z+bhn.z, hp.z);
            hv.w = gru1(gg[0].w+bir.w, gg[1].w+biz.w, gg[2].w+bin.w, gg[3].w+bhr.w, gg[4].w+bhz.w, gg[5].w+bhn.w, hp.w);
            *(float4*)(g_h + i*4) = hv;
            *(float4*)(out + (b*TSTEPS + t)*HDIM + j4) = hv;
        }
        gsync(G);
        // ---- C: hahe partials. 128 tasks = 16 tiles(128x128) x Ksplit8 (K=64) ----
        for (int task = bid; task < 128; task += G) {
            int kc = task & 7, tile = task >> 3;
            int n = tile & 7, m = tile >> 3;
            const float* Bptr = (n < 4) ? g_Wha + (size_t)n*128*HDIM + kc*64
                                        : W_he + (size_t)(n-4)*128*1536 + kc*64;
            ull acc2[4][4] = {};
            gemm128(g_h + (size_t)m*128*HDIM + kc*64, HDIM,
                    Bptr, (n < 4) ? HDIM : 1536, 4, As, Bs, acc2);
            float r[8][4]; unpack_acc(acc2, r);
            int ty = tid >> 5, tx = tid & 31;
            #pragma unroll
            for (int i = 0; i < 8; i++)
                *(float4*)&g_Hp[kc][(m*128 + ty*8 + i)*1024 + n*128 + tx*4] =
                    make_float4(r[i][0], r[i][1], r[i][2], r[i][3]);
        }
        gsync(G);
        // ---- D: 64 tasks x 4 rows: combine+relu, heads, z, x[t+1] ----
        for (int task = bid; task < 64; task += G) {
            int r0 = task*4;
            float* A8 = sm;          // 4 x 1028
            float* Ws = sm + 4112;   // 128 x 68
            __syncthreads();
            for (int e = tid; e < 4*1024; e += NTHR) {
                int r = e >> 10, c = e & 1023;
                int ro = (r0 + r)*1024 + c;
                float v = g_Hp[0][ro] + g_Hp[1][ro] + g_Hp[2][ro] + g_Hp[3][ro]
                        + g_Hp[4][ro] + g_Hp[5][ro] + g_Hp[6][ro] + g_Hp[7][ro];
                v += (c < 512) ? g_preHA[(t*BATCH + r0+r)*HDIM + c]
                               : g_preHE[(t*BATCH + r0+r)*HDIM + c - 512];
                A8[r*1028 + c] = fmaxf(v, 0.f);
            }
            const int c = tid & 127, rg = tid >> 7;
            const int aoff = (c < 64) ? 0 : 512;
            float acc = 0.f;
            for (int ch = 0; ch < 8; ch++) {
                __syncthreads();
                for (int e = tid; e < 512; e += NTHR) {
                    int c2 = e >> 2, k4 = (e & 3) << 4;
                    const float* Wr = (c2 < 64) ? W_prior + c2*HDIM : W_post + (c2-64)*HDIM;
                    #pragma unroll
                    for (int q = 0; q < 4; q++) {
                        float4 w = ld4(Wr + ch*64 + k4 + q*4);
                        Ws[c2*68 + k4 + q*4]   = w.x; Ws[c2*68 + k4 + q*4+1] = w.y;
                        Ws[c2*68 + k4 + q*4+2] = w.z; Ws[c2*68 + k4 + q*4+3] = w.w;
                    }
                }
                __syncthreads();
                const float* ab = A8 + rg*1028 + aoff + ch*64;
                #pragma unroll
                for (int k4 = 0; k4 < 64; k4 += 4) {
                    float4 w = ld4(Ws + c*68 + k4);
                    float4 a = ld4(ab + k4);
                    acc += a.x*w.x + a.y*w.y + a.z*w.z + a.w*w.w;
                }
            }
            __syncthreads();
            float* Q  = sm;        // 4 x 64 (A8 dead)
            float* zm = sm + 256;  // 4 x 32
            {
                int b = r0 + rg;
                float v = acc + ((c < 64) ? b_prior[c] : b_post[c-64]);
                if (c < 32)       out[OFF_PM + (b*TSTEPS + t)*ZDIM + c] = v;
                else if (c < 64)  out[OFF_PS + (b*TSTEPS + t)*ZDIM + c-32] = softplusf_(v);
                else              Q[rg*64 + (c-64)] = v;
            }
            __syncthreads();
            if (tid < 128) {
                int r = tid >> 5, j = tid & 31, b = r0 + r;
                float qm = Q[r*64 + j];
                float qs = softplusf_(Q[r*64 + 32 + j]);
                float z = qm + qs * post_noise[(b*TSTEPS + t)*ZDIM + j];
                int o = (b*TSTEPS + t)*ZDIM + j;
                out[OFF_QM + o] = qm; out[OFF_QS + o] = qs; out[OFF_Z + o] = z;
                if (t + 1 < TSTEPS)
                    zm[r*32 + j] = z * (1.f - dones[b*TSTEPS + t + 1]);
            }
            __syncthreads();
            if (t + 1 < TSTEPS) {
                for (int e = tid; e < 4*HDIM; e += NTHR) {
                    int r = e >> 9, cc = e & 511;
                    float acx = g_preAZ[((t+1)*BATCH + r0+r)*HDIM + cc];
                    #pragma unroll 8
                    for (int k = 0; k < ZDIM; k++)
                        acx += zm[r*32 + k] * g_WazzT[k*HDIM + cc];
                    g_x[(r0+r)*HDIM + cc] = fmaxf(acx, 0.f);
                }
            }
            __syncthreads();
        }
        if (t + 1 < TSTEPS) gsync(G);
    }
}

extern "C" void kernel_launch(void* const* d_in, const int* in_sizes, int n_in,
                              void* d_out, int out_size) {
    const float* prev_z = (const float*)d_in[0];
    const float* prev_h = (const float*)d_in[1];
    const float* actions = (const float*)d_in[2];
    const float* emb = (const float*)d_in[3];
    const float* dones = (const float*)d_in[4];
    const float* post_noise = (const float*)d_in[6];
    const float* W_az = (const float*)d_in[7];
    const float* b_az = (const float*)d_in[8];
    const float* W_ih = (const float*)d_in[9];
    const float* W_hh = (const float*)d_in[10];
    const float* b_ih = (const float*)d_in[11];
    const float* b_hh = (const float*)d_in[12];
    const float* W_ha = (const float*)d_in[13];
    const float* b_ha = (const float*)d_in[14];
    const float* W_prior = (const float*)d_in[15];
    const float* b_prior = (const float*)d_in[16];
    const float* W_he = (const float*)d_in[17];
    const float* b_he = (const float*)d_in[18];
    const float* W_post = (const float*)d_in[19];
    const float* b_post = (const float*)d_in[20];
    float* out = (float*)d_out;

    cudaFuncSetAttribute(rssm_kernel, cudaFuncAttributeMaxDynamicSharedMemorySize, SMEMB);
    int dev = 0, nsm = 0, occ = 0;
    cudaGetDevice(&dev);
    cudaDeviceGetAttribute(&nsm, cudaDevAttrMultiProcessorCount, dev);
    cudaOccupancyMaxActiveBlocksPerMultiprocessor(&occ, rssm_kernel, NTHR, SMEMB);
    if (occ < 1) occ = 1;
    int G = nsm * occ;
    if (G > 148) G = 148;
    rssm_kernel<<<G, NTHR, SMEMB>>>(prev_z, prev_h, actions, emb, dones, post_noise,
                                    W_az, b_az, W_ih, W_hh, b_ih, b_hh, W_ha, b_ha,
                                    W_prior, b_prior, W_he, b_he, W_post, b_post, out);
}

// round 12
// speedup vs baseline: 1.1207x; 1.0639x over previous
#include <cuda_runtime.h>
#include <math.h>

#define ADIM 6
#define ZDIM 32
#define HDIM 512
#define EDIM 1024
#define BATCH 256
#define TSTEPS 64
#define NTHR 512
#define SMEMB 53248

#define OFF_Z  (BATCH*TSTEPS*HDIM)
#define OFF_PM (OFF_Z + BATCH*TSTEPS*ZDIM)
#define OFF_PS (OFF_PM + BATCH*TSTEPS*ZDIM)
#define OFF_QM (OFF_PS + BATCH*TSTEPS*ZDIM)
#define OFF_QS (OFF_QM + BATCH*TSTEPS*ZDIM)

typedef unsigned long long ull;

// scratch. pre* layout: [t][b][h]
__device__ __align__(128) float g_preAZ[TSTEPS*BATCH*HDIM];
__device__ __align__(128) float g_preHA[TSTEPS*BATCH*HDIM];
__device__ __align__(128) float g_preHE[TSTEPS*BATCH*HDIM];
__device__ __align__(128) float g_Gp[3][BATCH*3072];
__device__ __align__(128) float g_Hp[8][BATCH*1024];
__device__ __align__(128) float g_h[BATCH*HDIM];
__device__ __align__(128) float g_x[BATCH*HDIM];
__device__ __align__(128) float g_z[BATCH*ZDIM];
__device__ __align__(128) float g_WazzT[ZDIM*HDIM];
__device__ __align__(128) float g_Wha[HDIM*HDIM];
__device__ volatile unsigned g_arrive = 0;
__device__ volatile unsigned g_epoch = 0;

__device__ __forceinline__ float sigmoidf_(float x) { return 1.f/(1.f+expf(-x)); }
__device__ __forceinline__ float softplusf_(float x) {
    return fmaxf(x, 0.f) + log1pf(expf(-fabsf(x)));
}
__device__ __forceinline__ float4 ld4(const float* p) { return *(const float4*)p; }
__device__ __forceinline__ float4 ld4cg(const float* p) { return __ldcg((const float4*)p); }
__device__ __forceinline__ void st4cg(float* p, float4 v) { __stcg((float4*)p, v); }

__device__ __forceinline__ ull pk2(float x) {
    ull r; asm("mov.b64 %0, {%1, %1};" : "=l"(r) : "f"(x)); return r;
}
__device__ __forceinline__ void ffma2(ull &d, ull a, ull b) {
    asm("fma.rn.f32x2 %0, %1, %2, %0;" : "+l"(d) : "l"(a), "l"(b));
}
__device__ __forceinline__ void unpk2(ull v, float &lo, float &hi) {
    asm("mov.b64 {%0, %1}, %2;" : "=f"(lo), "=f"(hi) : "l"(v));
}
union F4U { float4 f; ull u[2]; };

// Fence-free grid barrier: scoped release/acquire atomics only — no
// __threadfence, hence NO CCTL.IVALL L1 flush. All cross-block mutable data
// uses .cg (L2) accesses; read-only/write-once data stays L1-cached across
// phases. Monotonic epoch; reset happens-before epoch release-store.
__device__ __forceinline__ void gsync(int G) {
    __syncthreads();
    if (threadIdx.x == 0) {
        unsigned e = g_epoch;
        unsigned old;
        asm volatile("atom.acq_rel.gpu.global.add.u32 %0, [%1], %2;"
                     : "=r"(old) : "l"((unsigned*)&g_arrive), "r"(1u) : "memory");
        if (old == (unsigned)(G - 1)) {
            g_arrive = 0;
            asm volatile("st.release.gpu.global.u32 [%0], %1;"
                         :: "l"((unsigned*)&g_epoch), "r"(e + 1u) : "memory");
        } else {
            unsigned cur;
            do {
                __nanosleep(32);
                asm volatile("ld.acquire.gpu.global.u32 %0, [%1];"
                             : "=r"(cur) : "l"((unsigned*)&g_epoch) : "memory");
            } while (cur == e);
        }
    }
    __syncthreads();
}

// 128x128 tile GEMM, 512 thr, BK=16, micro 8x4 via FFMA2 (M-paired). acc += A*B^T
// ACG=1: A operand is recurrent data -> L1-bypass loads. B always normal (L1).
template<int ACG>
__device__ __forceinline__ void gemm128(
    const float* __restrict__ A, int lda, const float* __restrict__ B, int ldb,
    int KT, float* As, float* Bs, ull (&acc2)[4][4])
{
    const int tid = threadIdx.x;
    const int lr = tid >> 2, lk = (tid & 3) << 2;
    const int ty = tid >> 5, tx = tid & 31;
    const float* Ap = A + lr*lda + lk;
    const float* Bp = B + lr*ldb + lk;
    float4 av = ACG ? ld4cg(Ap) : ld4(Ap);
    float4 bv = ld4(Bp);
    #pragma unroll 1
    for (int kt = 1; kt <= KT; kt++) {
        __syncthreads();
        As[(lk+0)*132+lr]=av.x; As[(lk+1)*132+lr]=av.y; As[(lk+2)*132+lr]=av.z; As[(lk+3)*132+lr]=av.w;
        Bs[(lk+0)*132+lr]=bv.x; Bs[(lk+1)*132+lr]=bv.y; Bs[(lk+2)*132+lr]=bv.z; Bs[(lk+3)*132+lr]=bv.w;
        __syncthreads();
        if (kt < KT) {
            av = ACG ? ld4cg(Ap + kt*16) : ld4(Ap + kt*16);
            bv = ld4(Bp + kt*16);
        }
        #pragma unroll
        for (int kk = 0; kk < 16; kk++) {
            F4U a0, a1, b;
            a0.f = ld4(As + kk*132 + ty*8);
            a1.f = ld4(As + kk*132 + ty*8 + 4);
            b.f  = ld4(Bs + kk*132 + tx*4);
            ull au0 = a0.u[0], au1 = a0.u[1], au2 = a1.u[0], au3 = a1.u[1];
            ull b0 = pk2(b.f.x), b1 = pk2(b.f.y), b2 = pk2(b.f.z), b3 = pk2(b.f.w);
            ffma2(acc2[0][0], au0, b0); ffma2(acc2[0][1], au0, b1);
            ffma2(acc2[0][2], au0, b2); ffma2(acc2[0][3], au0, b3);
            ffma2(acc2[1][0], au1, b0); ffma2(acc2[1][1], au1, b1);
            ffma2(acc2[1][2], au1, b2); ffma2(acc2[1][3], au1, b3);
            ffma2(acc2[2][0], au2, b0); ffma2(acc2[2][1], au2, b1);
            ffma2(acc2[2][2], au2, b2); ffma2(acc2[2][3], au2, b3);
            ffma2(acc2[3][0], au3, b0); ffma2(acc2[3][1], au3, b1);
            ffma2(acc2[3][2], au3, b2); ffma2(acc2[3][3], au3, b3);
        }
    }
}

__device__ __forceinline__ void unpack_acc(ull (&acc2)[4][4], float (&r)[8][4]) {
    #pragma unroll
    for (int ip = 0; ip < 4; ip++)
        #pragma unroll
        for (int j = 0; j < 4; j++)
            unpk2(acc2[ip][j], r[2*ip][j], r[2*ip+1][j]);
}

__device__ __forceinline__ float gru1(float ir, float iz, float inn,
                                      float hr, float hz, float hn, float hp) {
    float rr = sigmoidf_(ir + hr);
    float u = sigmoidf_(iz + hz);
    float n = tanhf(inn + rr*hn);
    return (1.f - u)*n + u*hp;
}

__constant__ int c_kofs[3] = {0, 176, 352};
__constant__ int c_kcnt[3] = {11, 11, 10};

__global__ __launch_bounds__(NTHR, 1) void rssm_kernel(
    const float* __restrict__ prev_z, const float* __restrict__ prev_h,
    const float* __restrict__ actions, const float* __restrict__ emb,
    const float* __restrict__ dones, const float* __restrict__ post_noise,
    const float* __restrict__ W_az, const float* __restrict__ b_az,
    const float* __restrict__ W_ih, const float* __restrict__ W_hh,
    const float* __restrict__ b_ih, const float* __restrict__ b_hh,
    const float* __restrict__ W_ha, const float* __restrict__ b_ha,
    const float* __restrict__ W_prior, const float* __restrict__ b_prior,
    const float* __restrict__ W_he, const float* __restrict__ b_he,
    const float* __restrict__ W_post, const float* __restrict__ b_post,
    float* __restrict__ out)
{
    extern __shared__ __align__(16) float sm[];
    const int tid = threadIdx.x, bid = blockIdx.x, G = gridDim.x;
    const int gthr = G*NTHR, gtid = bid*NTHR + tid;
    float* As = sm;            // 16*132
    float* Bs = sm + 2112;     // 16*132

    // ===== P0: init, pack, action projections, preHE =====
    for (int i = gtid; i < BATCH*HDIM; i += gthr) g_h[i] = prev_h[i];
    for (int i = gtid; i < BATCH*ZDIM; i += gthr) g_z[i] = prev_z[i];
    for (int i = gtid; i < HDIM*HDIM; i += gthr)
        g_Wha[i] = W_ha[(i >> 9)*(HDIM+ADIM) + (i & 511)];
    for (int i = gtid; i < ZDIM*HDIM; i += gthr)
        g_WazzT[i] = W_az[(i & 511)*(ZDIM+ADIM) + (i >> 9)];
    for (int tt = bid; tt < TSTEPS; tt += G) {
        float* waz = sm, *wha = sm + 3072, *actS = sm + 6144;
        __syncthreads();
        for (int e = tid; e < HDIM*ADIM; e += NTHR) {
            int h = e / ADIM, j = e - h*ADIM;
            waz[e] = W_az[h*(ZDIM+ADIM) + ZDIM + j];
            wha[e] = W_ha[h*(HDIM+ADIM) + HDIM + j];
        }
        for (int e = tid; e < BATCH*ADIM; e += NTHR) {
            int b = e / ADIM, j = e - b*ADIM;
            actS[e] = actions[(b*TSTEPS + tt)*ADIM + j];
        }
        __syncthreads();
        for (int e = tid; e < BATCH*HDIM; e += NTHR) {
            int b = e >> 9, h = e & 511;
            float pa = b_az[h], ph = b_ha[h];
            #pragma unroll
            for (int j = 0; j < ADIM; j++) {
                float a = actS[b*ADIM + j];
                pa += a * waz[h*ADIM + j];
                ph += a * wha[h*ADIM + j];
            }
            int o = (tt*BATCH + b)*HDIM + h;
            g_preAZ[o] = pa; g_preHA[o] = ph;
        }
        __syncthreads();
    }
    // preHE: 512 tasks = 128 m-tiles x 4 n-tiles, K=1024 (KT=64)
    for (int task = bid; task < 512; task += G) {
        int n = task & 3, m = task >> 2;
        ull acc2[4][4] = {};
        gemm128<0>(emb + (size_t)m*128*EDIM, EDIM,
                   W_he + (size_t)n*128*1536 + 512, 1536, 64, As, Bs, acc2);
        float r[8][4]; unpack_acc(acc2, r);
        int ty = tid >> 5, tx = tid & 31;
        float4 bh = ld4(b_he + n*128 + tx*4);
        #pragma unroll
        for (int i = 0; i < 8; i++) {
            int rr = m*128 + ty*8 + i;
            int o = ((rr & 63)*BATCH + (rr >> 6))*HDIM + n*128 + tx*4;
            *(float4*)(g_preHE + o) = make_float4(r[i][0]+bh.x, r[i][1]+bh.y,
                                                  r[i][2]+bh.z, r[i][3]+bh.w);
        }
    }
    gsync(G);
    // ===== P1: x(0) =====
    for (int i = gtid; i < BATCH*HDIM; i += gthr) {
        int b = i >> 9, c = i & 511;
        float d = 1.f - dones[b*TSTEPS];
        float acx = g_preAZ[b*HDIM + c];
        #pragma unroll 8
        for (int k = 0; k < ZDIM; k++)
            acx += (g_z[b*ZDIM + k]*d) * g_WazzT[k*HDIM + c];
        __stcg(g_x + i, fmaxf(acx, 0.f));
    }
    gsync(G);

    for (int t = 0; t < TSTEPS; t++) {
        // ---- A: gate partials. 144 tasks = 48 tiles(128x128) x Ksplit3 ----
        for (int task = bid; task < 144; task += G) {
            int kc = task % 3, tile = task / 3;
            int n = tile % 24, m = tile / 24;
            int ko = c_kofs[kc];
            const float* Aptr = ((n < 12) ? g_x : g_h) + (size_t)m*128*HDIM + ko;
            const float* Bptr = ((n < 12) ? W_ih + (size_t)n*128*HDIM
                                          : W_hh + (size_t)(n-12)*128*HDIM) + ko;
            ull acc2[4][4] = {};
            gemm128<1>(Aptr, HDIM, Bptr, HDIM, c_kcnt[kc], As, Bs, acc2);
            float r[8][4]; unpack_acc(acc2, r);
            int ty = tid >> 5, tx = tid & 31;
            #pragma unroll
            for (int i = 0; i < 8; i++)
                st4cg(&g_Gp[kc][(m*128 + ty*8 + i)*3072 + n*128 + tx*4],
                      make_float4(r[i][0], r[i][1], r[i][2], r[i][3]));
        }
        gsync(G);
        // ---- B: combine 3 partials + GRU fuse + h_seq ----
        for (int i = gtid; i < BATCH*HDIM/4; i += gthr) {
            int b = i >> 7, j4 = (i & 127) << 2;
            const float* p0 = g_Gp[0] + b*3072 + j4;
            const float* p1 = g_Gp[1] + b*3072 + j4;
            const float* p2 = g_Gp[2] + b*3072 + j4;
            float4 gg[6];
            #pragma unroll
            for (int q = 0; q < 6; q++) {
                float4 a = ld4cg(p0 + q*512), bb = ld4cg(p1 + q*512), c = ld4cg(p2 + q*512);
                gg[q] = make_float4(a.x+bb.x+c.x, a.y+bb.y+c.y, a.z+bb.z+c.z, a.w+bb.w+c.w);
            }
            float4 bir = ld4(b_ih + j4), biz = ld4(b_ih + 512 + j4), bin = ld4(b_ih + 1024 + j4);
            float4 bhr = ld4(b_hh + j4), bhz = ld4(b_hh + 512 + j4), bhn = ld4(b_hh + 1024 + j4);
            float4 hp = ld4cg(g_h + i*4);
            float4 hv;
            hv.x = gru1(gg[0].x+bir.x, gg[1].x+biz.x, gg[2].x+bin.x, gg[3].x+bhr.x, gg[4].x+bhz.x, gg[5].x+bhn.x, hp.x);
            hv.y = gru1(gg[0].y+bir.y, gg[1].y+biz.y, gg[2].y+bin.y, gg[3].y+bhr.y, gg[4].y+bhz.y, gg[5].y+bhn.y, hp.y);
            hv.z = gru1(gg[0].z+bir.z, gg[1].z+biz.z, gg[2].z+bin.z, gg[3].z+bhr.z, gg[4].z+bhz.z, gg[5].z+bhn.z, hp.z);
            hv.w = gru1(gg[0].w+bir.w, gg[1].w+biz.w, gg[2].w+bin.w, gg[3].w+bhr.w, gg[4].w+bhz.w, gg[5].w+bhn.w, hp.w);
            st4cg(g_h + i*4, hv);
            *(float4*)(out + (b*TSTEPS + t)*HDIM + j4) = hv;
        }
        gsync(G);
        // ---- C: hahe partials. 128 tasks = 16 tiles(128x128) x Ksplit8 (K=64) ----
        for (int task = bid; task < 128; task += G) {
            int kc = task & 7, tile = task >> 3;
            int n = tile & 7, m = tile >> 3;
            const float* Bptr = (n < 4) ? g_Wha + (size_t)n*128*HDIM + kc*64
                                        : W_he + (size_t)(n-4)*128*1536 + kc*64;
            ull acc2[4][4] = {};
            gemm128<1>(g_h + (size_t)m*128*HDIM + kc*64, HDIM,
                       Bptr, (n < 4) ? HDIM : 1536, 4, As, Bs, acc2);
            float r[8][4]; unpack_acc(acc2, r);
            int ty = tid >> 5, tx = tid & 31;
            #pragma unroll
            for (int i = 0; i < 8; i++)
                st4cg(&g_Hp[kc][(m*128 + ty*8 + i)*1024 + n*128 + tx*4],
                      make_float4(r[i][0], r[i][1], r[i][2], r[i][3]));
        }
        gsync(G);
        // ---- D: 64 tasks x 4 rows: combine+relu, heads, z, x[t+1] ----
        for (int task = bid; task < 64; task += G) {
            int r0 = task*4;
            float* A8 = sm;          // 4 x 1028
            float* Ws = sm + 4112;   // 128 x 68
            __syncthreads();
            for (int e = tid; e < 4*1024; e += NTHR) {
                int r = e >> 10, c = e & 1023;
                int ro = (r0 + r)*1024 + c;
                float v = __ldcg(g_Hp[0]+ro) + __ldcg(g_Hp[1]+ro)
                        + __ldcg(g_Hp[2]+ro) + __ldcg(g_Hp[3]+ro)
                        + __ldcg(g_Hp[4]+ro) + __ldcg(g_Hp[5]+ro)
                        + __ldcg(g_Hp[6]+ro) + __ldcg(g_Hp[7]+ro);
                v += (c < 512) ? g_preHA[(t*BATCH + r0+r)*HDIM + c]
                               : g_preHE[(t*BATCH + r0+r)*HDIM + c - 512];
                A8[r*1028 + c] = fmaxf(v, 0.f);
            }
            const int c = tid & 127, rg = tid >> 7;
            const int aoff = (c < 64) ? 0 : 512;
            float acc = 0.f;
            for (int ch = 0; ch < 8; ch++) {
                __syncthreads();
                for (int e = tid; e < 512; e += NTHR) {
                    int c2 = e >> 2, k4 = (e & 3) << 4;
                    const float* Wr = (c2 < 64) ? W_prior + c2*HDIM : W_post + (c2-64)*HDIM;
                    #pragma unroll
                    for (int q = 0; q < 4; q++) {
                        float4 w = ld4(Wr + ch*64 + k4 + q*4);
                        Ws[c2*68 + k4 + q*4]   = w.x; Ws[c2*68 + k4 + q*4+1] = w.y;
                        Ws[c2*68 + k4 + q*4+2] = w.z; Ws[c2*68 + k4 + q*4+3] = w.w;
                    }
                }
                __syncthreads();
                const float* ab = A8 + rg*1028 + aoff + ch*64;
                #pragma unroll
                for (int k4 = 0; k4 < 64; k4 += 4) {
                    float4 w = ld4(Ws + c*68 + k4);
                    float4 a = ld4(ab + k4);
                    acc += a.x*w.x + a.y*w.y + a.z*w.z + a.w*w.w;
                }
            }
            __syncthreads();
            float* Q  = sm;        // 4 x 64 (A8 dead)
            float* zm = sm + 256;  // 4 x 32
            {
                int b = r0 + rg;
                float v = acc + ((c < 64) ? b_prior[c] : b_post[c-64]);
                if (c < 32)       out[OFF_PM + (b*TSTEPS + t)*ZDIM + c] = v;
                else if (c < 64)  out[OFF_PS + (b*TSTEPS + t)*ZDIM + c-32] = softplusf_(v);
                else              Q[rg*64 + (c-64)] = v;
            }
            __syncthreads();
            if (tid < 128) {
                int r = tid >> 5, j = tid & 31, b = r0 + r;
                float qm = Q[r*64 + j];
                float qs = softplusf_(Q[r*64 + 32 + j]);
                float z = qm + qs * post_noise[(b*TSTEPS + t)*ZDIM + j];
                int o = (b*TSTEPS + t)*ZDIM + j;
                out[OFF_QM + o] = qm; out[OFF_QS + o] = qs; out[OFF_Z + o] = z;
                if (t + 1 < TSTEPS)
                    zm[r*32 + j] = z * (1.f - dones[b*TSTEPS + t + 1]);
            }
            __syncthreads();
            if (t + 1 < TSTEPS) {
                for (int e = tid; e < 4*HDIM; e += NTHR) {
                    int r = e >> 9, cc = e & 511;
                    float acx = g_preAZ[((t+1)*BATCH + r0+r)*HDIM + cc];
                    #pragma unroll 8
                    for (int k = 0; k < ZDIM; k++)
                        acx += zm[r*32 + k] * g_WazzT[k*HDIM + cc];
                    __stcg(g_x + (r0+r)*HDIM + cc, fmaxf(acx, 0.f));
                }
            }
            __syncthreads();
        }
        if (t + 1 < TSTEPS) gsync(G);
    }
}

extern "C" void kernel_launch(void* const* d_in, const int* in_sizes, int n_in,
                              void* d_out, int out_size) {
    const float* prev_z = (const float*)d_in[0];
    const float* prev_h = (const float*)d_in[1];
    const float* actions = (const float*)d_in[2];
    const float* emb = (const float*)d_in[3];
    const float* dones = (const float*)d_in[4];
    const float* post_noise = (const float*)d_in[6];
    const float* W_az = (const float*)d_in[7];
    const float* b_az = (const float*)d_in[8];
    const float* W_ih = (const float*)d_in[9];
    const float* W_hh = (const float*)d_in[10];
    const float* b_ih = (const float*)d_in[11];
    const float* b_hh = (const float*)d_in[12];
    const float* W_ha = (const float*)d_in[13];
    const float* b_ha = (const float*)d_in[14];
    const float* W_prior = (const float*)d_in[15];
    const float* b_prior = (const float*)d_in[16];
    const float* W_he = (const float*)d_in[17];
    const float* b_he = (const float*)d_in[18];
    const float* W_post = (const float*)d_in[19];
    const float* b_post = (const float*)d_in[20];
    float* out = (float*)d_out;

    cudaFuncSetAttribute(rssm_kernel, cudaFuncAttributeMaxDynamicSharedMemorySize, SMEMB);
    int dev = 0, nsm = 0, occ = 0;
    cudaGetDevice(&dev);
    cudaDeviceGetAttribute(&nsm, cudaDevAttrMultiProcessorCount, dev);
    cudaOccupancyMaxActiveBlocksPerMultiprocessor(&occ, rssm_kernel, NTHR, SMEMB);
    if (occ < 1) occ = 1;
    int G = nsm * occ;
    if (G > 148) G = 148;
    rssm_kernel<<<G, NTHR, SMEMB>>>(prev_z, prev_h, actions, emb, dones, post_noise,
                                    W_az, b_az, W_ih, W_hh, b_ih, b_hh, W_ha, b_ha,
                                    W_prior, b_prior, W_he, b_he, W_post, b_post, out);
}